// round 17
// baseline (speedup 1.0000x reference)
#include <cuda_runtime.h>
#include <math.h>

#define NS     64
#define HID    20
#define HDIM   1280
#define BATCH  16384
#define MROWS  8
#define T      384             // 12 warps = 4 levels x 3 warps, reg cap 168
#define NJW    48              // j-stride per level (3 warp-groups x 16 j)
#define LSTR   (HDIM * MROWS)  // 10240 floats per pre level, [col][row8]
#define LVL    806400          // 2016*400 floats per level

typedef unsigned long long ull;

// Chunk-major scatter weights (best measured layout):
//   slab si (nt=(63-si)*20 targets): float4 at [k*nt + j] = W[j][4k..4k+3]
__device__ float g_Ws4[4 * LVL];
__device__ float g_W1s[2016 * 20];      // fc1 scalar, j-major
__device__ float g_W6s[2016 * 20];      // fc6 chunk-major: (k, t) float4
__device__ float g_Wd [64 * 2020];      // diag per si: [lv*400 + ci*20 + c], fc6 at 2000

__device__ __forceinline__ int slab_off1(int si) { return 63 * si - (si * (si - 1)) / 2; }

__global__ void prep_scatter(const float* __restrict__ W1, const float* __restrict__ W2,
                             const float* __restrict__ W3, const float* __restrict__ W4,
                             const float* __restrict__ W5, const float* __restrict__ W6)
{
    const int si = blockIdx.x, what = blockIdx.y;
    const int nso1 = 63 - si;
    const int nt = nso1 * 20;
    if (what < 4) {
        const float* W = (what == 0) ? W2 : (what == 1) ? W3 : (what == 2) ? W4 : W5;
        float* dst = g_Ws4 + (size_t)what * LVL + (size_t)slab_off1(si) * 400;
        const int cnt = nso1 * 400;
        for (int t = threadIdx.x; t < cnt; t += blockDim.x) {
            int m = t & 3, q = t >> 2;
            int j = q % nt, k = q / nt;
            int so = si + 1 + j / 20, c = j % 20, ci = 4 * k + m;
            dst[t] = W[(size_t)(c * NS + so) * HDIM + ci * NS + si];
        }
    } else if (what == 4) {
        float* d1 = g_W1s + (size_t)slab_off1(si) * 20;
        for (int t = threadIdx.x; t < nt; t += blockDim.x) {
            int so = si + 1 + t / 20, c = t % 20;
            d1[t] = W1[(size_t)(c * NS + so) * NS + si];
        }
        float* dd = g_Wd + (size_t)si * 2020;
        for (int t = threadIdx.x; t < 2020; t += blockDim.x) {
            if (t < 1600) {
                int lv = t / 400, rem = t - lv * 400;
                int ci = rem / 20, c = rem - ci * 20;
                const float* W = (lv == 0) ? W2 : (lv == 1) ? W3 : (lv == 2) ? W4 : W5;
                dd[t] = W[(size_t)(c * NS + si) * HDIM + ci * NS + si];
            } else if (t < 2000) {
                dd[t] = 0.0f;
            } else {
                dd[t] = W6[(size_t)si * HDIM + (t - 2000) * NS + si];
            }
        }
    } else {
        float* d6 = g_W6s + (size_t)slab_off1(si) * 20;
        const int cnt = nso1 * 20;
        for (int t = threadIdx.x; t < cnt; t += blockDim.x) {
            int m = t & 3, q = t >> 2;
            int tt = q % nso1, k = q / nso1;
            int so = si + 1 + tt, ci = 4 * k + m;
            d6[t] = W6[(size_t)so * HDIM + ci * NS + si];
        }
    }
}

__device__ __forceinline__ ull ffma2(ull a, ull b, ull c)
{
    ull d;
    asm("fma.rn.f32x2 %0, %1, %2, %3;" : "=l"(d) : "l"(a), "l"(b), "l"(c));
    return d;
}
__device__ __forceinline__ ull pack2(float lo, float hi)
{
    ull v;
    asm("mov.b64 %0, {%1, %2};" : "=l"(v) : "f"(lo), "f"(hi));
    return v;
}
__device__ __forceinline__ float hsum2(ull v)
{
    float lo, hi;
    asm("mov.b64 {%0, %1}, %2;" : "=f"(lo), "=f"(hi) : "l"(v));
    return lo + hi;
}
__device__ __forceinline__ float sigmoidf(float x) { return 1.0f / (1.0f + expf(-x)); }

#define BAR_DIAG() asm volatile("bar.sync 1, 160;" ::: "memory")

// pipeline stage: 5 weight chunks + float4 dst (own 4 rows at col j)
#define WLOAD4(W, D, j) do {                                                    \
    (W)[0] = *(const ulonglong2*)(wb + ((size_t)0 * nt + (j)) * 4);             \
    (W)[1] = *(const ulonglong2*)(wb + ((size_t)1 * nt + (j)) * 4);             \
    (W)[2] = *(const ulonglong2*)(wb + ((size_t)2 * nt + (j)) * 4);             \
    (W)[3] = *(const ulonglong2*)(wb + ((size_t)3 * nt + (j)) * 4);             \
    (W)[4] = *(const ulonglong2*)(wb + ((size_t)4 * nt + (j)) * 4);             \
    (D) = *(const float4*)(prl + (size_t)(j) * 8 + rb);                         \
} while (0)

// compute stage: 80-MAC (4 rows x 20 ci), fold prefetched dst, float4 store
#define WCOMP4(W, D, j) do {                                                    \
    ull a0 = 0ull, a1 = 0ull, a2 = 0ull, a3 = 0ull;                             \
    _Pragma("unroll")                                                           \
    for (int k = 0; k < 5; ++k) {                                               \
        a0 = ffma2((W)[k].x, hh[0][2*k],   a0);                                 \
        a1 = ffma2((W)[k].x, hh[1][2*k],   a1);                                 \
        a2 = ffma2((W)[k].x, hh[2][2*k],   a2);                                 \
        a3 = ffma2((W)[k].x, hh[3][2*k],   a3);                                 \
        a0 = ffma2((W)[k].y, hh[0][2*k+1], a0);                                 \
        a1 = ffma2((W)[k].y, hh[1][2*k+1], a1);                                 \
        a2 = ffma2((W)[k].y, hh[2][2*k+1], a2);                                 \
        a3 = ffma2((W)[k].y, hh[3][2*k+1], a3);                                 \
    }                                                                           \
    float4 o_;                                                                  \
    o_.x = hsum2(a0) + (D).x;                                                   \
    o_.y = hsum2(a1) + (D).y;                                                   \
    o_.z = hsum2(a2) + (D).z;                                                   \
    o_.w = hsum2(a3) + (D).w;                                                   \
    *(float4*)(prl + (size_t)(j) * 8 + rb) = o_;                                \
} while (0)

__global__ void __launch_bounds__(T, 1)
net_kernel(const float* __restrict__ u, float* __restrict__ out)
{
    extern __shared__ float sm[];
    float* pre  = sm;                        // [5][1280][8]  col-major rows
    float* pre6 = pre + 5 * LSTR;            // [64][8]
    float* hbt  = pre6 + NS * MROWS;         // [5][8][20]
    float* usm  = hbt + 5 * 160;             // [8][64]
    float* wd   = usm + 512;                 // [2020]
    float* sv   = wd + 2020;                 // [8]  (ull-viewable, 8B aligned)

    const int tid  = threadIdx.x;
    const int lane = tid & 31;
    const int wid  = tid >> 5;
    const int lv   = wid & 3;                    // this warp's scatter level
    const int wgrp = wid >> 2;                   // 0..2
    const int jw   = wgrp * 16 + (lane >> 1);    // j-lane within level: 0..47
    const int grp  = lane & 1;                   // row group (rows grp*4..grp*4+3)
    const int rb   = grp * 4;
    // fc6 lanes (2-row mapping, once per step)
    const int pair = tid & 3, jl = tid >> 2;
    const int r0 = 2 * pair;

    for (int k = tid; k < 5 * LSTR; k += T) pre[k] = 0.0f;
    for (int k = tid; k < NS * MROWS; k += T) pre6[k] = 0.0f;
    for (int k = tid; k < 512; k += T) {
        int ii = k >> 3, rr = k & 7;
        usm[rr * NS + ii] = u[(size_t)ii * BATCH + (size_t)blockIdx.x * MROWS + rr];
    }
    for (int k = tid; k < 2020; k += T) wd[k] = g_Wd[k];
    __syncthreads();

    for (int i = 0; i < NS; ++i) {
        // ===== diagonal chain: 160 threads (warps 0-4) =====
        if (tid < 160) {
            const int dr = tid / 20, dc = tid - (tid / 20) * 20;
            hbt[dr * 20 + dc] = sigmoidf(pre[(i * HID + dc) * 8 + dr]);
            BAR_DIAG();
            #pragma unroll 1
            for (int dlv = 0; dlv < 4; ++dlv) {
                float acc = pre[(size_t)(dlv + 1) * LSTR + (i * HID + dc) * 8 + dr];
                float acc2 = 0.0f;
                const float* w   = wd + dlv * 400 + dc;
                const float* hh_ = hbt + dlv * 160 + dr * 20;
                #pragma unroll
                for (int ci = 0; ci < 10; ++ci) {
                    acc  = fmaf(w[(2 * ci)     * 20], hh_[2 * ci],     acc);
                    acc2 = fmaf(w[(2 * ci + 1) * 20], hh_[2 * ci + 1], acc2);
                }
                hbt[(dlv + 1) * 160 + dr * 20 + dc] = sigmoidf(acc + acc2);
                BAR_DIAG();
            }
            if (tid < MROWS) {                           // fc6 diag + sample
                float acc = pre6[i * 8 + tid];
                const float* hh_ = hbt + 4 * 160 + tid * 20;
                #pragma unroll
                for (int ci = 0; ci < 20; ++ci) acc = fmaf(wd[2000 + ci], hh_[ci], acc);
                float x = sigmoidf(acc);
                out[((size_t)blockIdx.x * MROWS + tid) * NS + i] = x;
                sv[tid] = (x >= usm[tid * NS + i]) ? 1.0f : -1.0f;
            }
        }
        __syncthreads();

        // ===== scatter phase =====
        if (i < 63) {
            const int nso1 = 63 - i;
            const int nt = nso1 * HID;
            const int tbase = (i + 1) * HID;
            const size_t soff = (size_t)slab_off1(i);

            // fc2..fc5 — level-per-warp, 4 rows/lane, float4 dst RMW,
            // 2-deep ping-pong on weights+dst (R13 structure, fewer LSU ops)
            {
                const float* wb = g_Ws4 + (size_t)lv * LVL + soff * 400;
                float* prl = pre + (size_t)(lv + 1) * LSTR + (size_t)tbase * 8;
                ull hh[4][10];
                #pragma unroll
                for (int t = 0; t < 4; ++t) {
                    const ull* hp = (const ull*)(hbt + lv * 160 + (rb + t) * 20);
                    #pragma unroll
                    for (int q = 0; q < 10; ++q) hh[t][q] = hp[q];
                }
                int j0 = jw;
                if (j0 < nt) {
                    ulonglong2 wA[5], wB[5];
                    float4 dA, dB;
                    WLOAD4(wA, dA, j0);
                    for (;;) {
                        int j1 = j0 + NJW;
                        if (j1 >= nt) { WCOMP4(wA, dA, j0); break; }
                        WLOAD4(wB, dB, j1);
                        WCOMP4(wA, dA, j0);
                        j0 = j1 + NJW;
                        if (j0 >= nt) { WCOMP4(wB, dB, j1); break; }
                        WLOAD4(wA, dA, j0);
                        WCOMP4(wB, dB, j1);
                    }
                }
            }
            // fc6 (single round, lanes jl < nso1; 2 rows per lane)
            if (jl < nso1) {
                const float* wb6 = g_W6s + soff * 20;
                const ull* hp0 = (const ull*)(hbt + 4 * 160 + r0 * 20);
                const ull* hp1 = (const ull*)(hbt + 4 * 160 + (r0 + 1) * 20);
                float* dpf = pre6 + (size_t)(i + 1 + jl) * 8 + r0;
                float dd0 = dpf[0], dd1 = dpf[1];
                ull a0 = 0ull, a1 = 0ull;
                #pragma unroll
                for (int k = 0; k < 5; ++k) {
                    ulonglong2 wv = *(const ulonglong2*)(wb6 + ((size_t)k * nso1 + jl) * 4);
                    a0 = ffma2(wv.x, hp0[2 * k], a0); a0 = ffma2(wv.y, hp0[2 * k + 1], a0);
                    a1 = ffma2(wv.x, hp1[2 * k], a1); a1 = ffma2(wv.y, hp1[2 * k + 1], a1);
                }
                dpf[0] = hsum2(a0) + dd0;
                dpf[1] = hsum2(a1) + dd1;
            }
            // fc1 rank-1 — 2 threads per column, float4 halves (conflict-free)
            {
                const float* wb1 = g_W1s + soff * 20;
                const ull* sv64 = (const ull*)sv;     // (s0,s1)(s2,s3)(s4,s5)(s6,s7)
                #pragma unroll 1
                for (int t = tid; t < 2 * nt; t += T) {
                    int j = t >> 1, half = t & 1;
                    float w = wb1[j];
                    ull w2 = pack2(w, w);
                    ull sa = sv64[half * 2], sb = sv64[half * 2 + 1];
                    ull* d = (ull*)(pre + (size_t)(tbase + j) * 8 + half * 4);
                    ulonglong2 dv = *(ulonglong2*)d;
                    dv.x = ffma2(w2, sa, dv.x);
                    dv.y = ffma2(w2, sb, dv.y);
                    *(ulonglong2*)d = dv;
                }
            }
            // prefetch next step's diag weights
            {
                const float* src = g_Wd + (size_t)(i + 1) * 2020;
                for (int k = tid; k < 2020; k += T) wd[k] = src[k];
            }
        }
        __syncthreads();
    }
}

extern "C" void kernel_launch(void* const* d_in, const int* in_sizes, int n_in,
                              void* d_out, int out_size)
{
    (void)in_sizes; (void)n_in; (void)out_size;
    const float* u  = (const float*)d_in[1];
    const float* W1 = (const float*)d_in[2];
    const float* W2 = (const float*)d_in[3];
    const float* W3 = (const float*)d_in[4];
    const float* W4 = (const float*)d_in[5];
    const float* W5 = (const float*)d_in[6];
    const float* W6 = (const float*)d_in[7];
    float* out = (float*)d_out;

    dim3 pg(64, 6);
    prep_scatter<<<pg, 256>>>(W1, W2, W3, W4, W5, W6);

    const int smem_bytes = (5 * LSTR + NS * MROWS + 5 * 160
                            + 512 + 2020 + 8) * (int)sizeof(float);   // ~220 KB
    cudaFuncSetAttribute(net_kernel, cudaFuncAttributeMaxDynamicSharedMemorySize, smem_bytes);
    net_kernel<<<BATCH / MROWS, T, smem_bytes>>>(u, out);
}